// round 6
// baseline (speedup 1.0000x reference)
#include <cuda_runtime.h>
#include <cuda_bf16.h>

#define N_NEURON 128
#define N_RULES  512
#define BATCH    4096

// Fully fused: one warp per batch element b (R2 decomposition, best so far),
// plus register-free L2 prefetch of x two iterations (4 neurons) ahead.
__global__ void __launch_bounds__(128, 8) lei_fused_kernel(
    const float* __restrict__ x,
    const float* __restrict__ head_w,
    const float* __restrict__ head_b,
    const float* __restrict__ foot_w,
    const float* __restrict__ foot_b,
    float* __restrict__ out)
{
    const int warp = threadIdx.x >> 5;
    const int lane = threadIdx.x & 31;
    const int b = blockIdx.x * 4 + warp;   // 1024 blocks * 4 warps = 4096

    const float* __restrict__ fw0 = foot_w;            // [128]
    const float* __restrict__ fw1 = foot_w + N_NEURON; // [128]

    float acc0 = 0.0f, acc1 = 0.0f;

    // Fold head-bias contribution: sum_n head_b[n]*fw_j[n], split across lanes.
#pragma unroll
    for (int k = 0; k < 4; k++) {
        int n = 32 * k + lane;
        float hb = head_b[n];
        acc0 = fmaf(hb, fw0[n], acc0);
        acc1 = fmaf(hb, fw1[n], acc1);
    }

    const size_t nstride = (size_t)BATCH * (N_RULES / 4);  // float4 stride between neurons
    const float4* __restrict__ xp =
        reinterpret_cast<const float4*>(x) + (size_t)b * (N_RULES / 4) + lane;
    const float4* __restrict__ wp =
        reinterpret_cast<const float4*>(head_w) + lane;

    // Per-lane prefetch offset (in float4 units) relative to the warp's row start:
    // lanes 0-15 cover row n+4 (16 x 128B = 2KB), lanes 16-31 cover row n+5.
    const size_t pf_off = (size_t)(lane & 15) * 8 + (size_t)(lane >> 4) * nstride;

    for (int n = 0; n < N_NEURON; n += 2) {
        // Register-free L2 prefetch of the rows two iterations ahead.
        if (n + 4 < N_NEURON) {
            const float4* pfa = (xp - lane) + 4 * nstride + pf_off;
            asm volatile("prefetch.global.L2 [%0];" :: "l"(pfa));
        }

        // Front-batch 8 streaming x loads (2 neurons' rows) for MLP.
        const float4* p0 = xp;
        const float4* p1 = xp + nstride;
        float4 xv[8];
#pragma unroll
        for (int k = 0; k < 4; k++) xv[k]     = __ldcs(p0 + 32 * k);
#pragma unroll
        for (int k = 0; k < 4; k++) xv[4 + k] = __ldcs(p1 + 32 * k);
        xp += 2 * nstride;

        float pa = 0.0f, pb = 0.0f;
#pragma unroll
        for (int k = 0; k < 4; k++) {
            float4 wv = wp[32 * k];
            pa = fmaf(xv[k].x, wv.x, pa);
            pa = fmaf(xv[k].y, wv.y, pa);
            pa = fmaf(xv[k].z, wv.z, pa);
            pa = fmaf(xv[k].w, wv.w, pa);
        }
#pragma unroll
        for (int k = 0; k < 4; k++) {
            float4 wv = wp[(N_RULES / 4) + 32 * k];
            pb = fmaf(xv[4 + k].x, wv.x, pb);
            pb = fmaf(xv[4 + k].y, wv.y, pb);
            pb = fmaf(xv[4 + k].z, wv.z, pb);
            pb = fmaf(xv[4 + k].w, wv.w, pb);
        }
        wp += 2 * (N_RULES / 4);

        acc0 = fmaf(pa, fw0[n], acc0);
        acc1 = fmaf(pa, fw1[n], acc1);
        acc0 = fmaf(pb, fw0[n + 1], acc0);
        acc1 = fmaf(pb, fw1[n + 1], acc1);
    }

    // Warp reduction of the two logit accumulators.
#pragma unroll
    for (int off = 16; off; off >>= 1) {
        acc0 += __shfl_xor_sync(0xFFFFFFFFu, acc0, off);
        acc1 += __shfl_xor_sync(0xFFFFFFFFu, acc1, off);
    }

    if (lane == 0) {
        float l0 = acc0 + foot_b[0];
        float l1 = acc1 + foot_b[1];
        float m = fmaxf(l0, l1);
        float e0 = __expf(l0 - m);
        float e1 = __expf(l1 - m);
        float inv = 1.0f / (e0 + e1);
        out[b * 2 + 0] = e0 * inv;
        out[b * 2 + 1] = e1 * inv;
    }
}

extern "C" void kernel_launch(void* const* d_in, const int* in_sizes, int n_in,
                              void* d_out, int out_size)
{
    const float* x      = (const float*)d_in[0];
    const float* head_w = (const float*)d_in[1];
    const float* head_b = (const float*)d_in[2];
    const float* foot_w = (const float*)d_in[3];
    const float* foot_b = (const float*)d_in[4];
    float* out = (float*)d_out;

    lei_fused_kernel<<<BATCH / 4, 128>>>(x, head_w, head_b, foot_w, foot_b, out);
}

// round 7
// speedup vs baseline: 1.1496x; 1.1496x over previous
#include <cuda_runtime.h>
#include <cuda_bf16.h>

#define N_NEURON 128
#define N_RULES  512
#define BATCH    4096

// Fully fused: one warp per batch element b.
// logit_j[b] = sum_n foot_w[j,n] * ( x[n,b,:].head_w[n,:] + head_b[n] ) + foot_b[j]
// Per-lane weighted accumulation; single warp-reduce at the end; softmax on lane 0.
// 8 front-batched LDG.128 per warp per iteration (2 neuron rows) — measured-best
// balance of in-flight bytes vs register pressure (regs=64, 7 CTAs/SM).
__global__ void __launch_bounds__(128, 8) lei_fused_kernel(
    const float* __restrict__ x,
    const float* __restrict__ head_w,
    const float* __restrict__ head_b,
    const float* __restrict__ foot_w,
    const float* __restrict__ foot_b,
    float* __restrict__ out)
{
    const int warp = threadIdx.x >> 5;
    const int lane = threadIdx.x & 31;
    const int b = blockIdx.x * 4 + warp;   // 1024 blocks * 4 warps = 4096

    const float* __restrict__ fw0 = foot_w;            // [128]
    const float* __restrict__ fw1 = foot_w + N_NEURON; // [128]

    float acc0 = 0.0f, acc1 = 0.0f;

    // Fold the head bias contribution: sum_n head_b[n]*fw_j[n], split across lanes.
#pragma unroll
    for (int k = 0; k < 4; k++) {
        int n = 32 * k + lane;
        float hb = head_b[n];
        acc0 = fmaf(hb, fw0[n], acc0);
        acc1 = fmaf(hb, fw1[n], acc1);
    }

    const float4* __restrict__ xb =
        reinterpret_cast<const float4*>(x) + (size_t)b * (N_RULES / 4);
    const size_t nstride = (size_t)BATCH * (N_RULES / 4);  // float4 stride between neurons
    const float4* __restrict__ wq = reinterpret_cast<const float4*>(head_w);

    for (int n = 0; n < N_NEURON; n += 2) {
        // Front-batch 8 x loads (2 neurons' rows) for MLP.
        const float4* p0 = xb + (size_t)n * nstride;
        const float4* p1 = p0 + nstride;
        float4 xv[8];
#pragma unroll
        for (int k = 0; k < 4; k++) xv[k] = p0[lane + 32 * k];
#pragma unroll
        for (int k = 0; k < 4; k++) xv[4 + k] = p1[lane + 32 * k];

        float pa = 0.0f, pb = 0.0f;
#pragma unroll
        for (int k = 0; k < 4; k++) {
            float4 wv = wq[(size_t)n * (N_RULES / 4) + lane + 32 * k];
            pa = fmaf(xv[k].x, wv.x, pa);
            pa = fmaf(xv[k].y, wv.y, pa);
            pa = fmaf(xv[k].z, wv.z, pa);
            pa = fmaf(xv[k].w, wv.w, pa);
        }
#pragma unroll
        for (int k = 0; k < 4; k++) {
            float4 wv = wq[(size_t)(n + 1) * (N_RULES / 4) + lane + 32 * k];
            pb = fmaf(xv[4 + k].x, wv.x, pb);
            pb = fmaf(xv[4 + k].y, wv.y, pb);
            pb = fmaf(xv[4 + k].z, wv.z, pb);
            pb = fmaf(xv[4 + k].w, wv.w, pb);
        }

        acc0 = fmaf(pa, fw0[n], acc0);
        acc1 = fmaf(pa, fw1[n], acc1);
        acc0 = fmaf(pb, fw0[n + 1], acc0);
        acc1 = fmaf(pb, fw1[n + 1], acc1);
    }

    // Warp reduction of the two logit accumulators.
#pragma unroll
    for (int off = 16; off; off >>= 1) {
        acc0 += __shfl_xor_sync(0xFFFFFFFFu, acc0, off);
        acc1 += __shfl_xor_sync(0xFFFFFFFFu, acc1, off);
    }

    if (lane == 0) {
        float l0 = acc0 + foot_b[0];
        float l1 = acc1 + foot_b[1];
        float m  = fmaxf(l0, l1);
        float e0 = __expf(l0 - m);
        float e1 = __expf(l1 - m);
        float inv = 1.0f / (e0 + e1);
        out[b * 2 + 0] = e0 * inv;
        out[b * 2 + 1] = e1 * inv;
    }
}

extern "C" void kernel_launch(void* const* d_in, const int* in_sizes, int n_in,
                              void* d_out, int out_size)
{
    const float* x      = (const float*)d_in[0];
    const float* head_w = (const float*)d_in[1];
    const float* head_b = (const float*)d_in[2];
    const float* foot_w = (const float*)d_in[3];
    const float* foot_b = (const float*)d_in[4];
    float* out = (float*)d_out;

    // 4096 warps total, one per batch element: 1024 blocks x 128 threads.
    lei_fused_kernel<<<BATCH / 4, 128>>>(x, head_w, head_b, foot_w, foot_b, out);
}

// round 8
// speedup vs baseline: 1.1533x; 1.0033x over previous
#include <cuda_runtime.h>
#include <cuda_bf16.h>

#define N_NEURON 128
#define N_RULES  512
#define BATCH    4096

// Fully fused: one warp per batch element b.
// logit_j[b] = sum_n foot_w[j,n] * ( x[n,b,:].head_w[n,:] + head_b[n] ) + foot_b[j]
// Per-lane weighted accumulation; single warp-reduce at the end; softmax on lane 0.
//
// Converged configuration (R2, best measured 155.7us):
//  - 8 front-batched LDG.128 per warp per iteration (2 neuron rows, 113 KB/SM in flight)
//  - regs=64 -> 8 CTAs/SM schedulable, grid 1024 single-wave
//  - head_w (256 KB) cache-resident: measured DRAM bytes == sizeof(x) exactly
// Achieved 6.90 TB/s == B300 LTS chip cap (~6300 B/cyc, path-independent) ->
// at the hardware ceiling; more warps / prefetch / ldcs all measured <= neutral.
__global__ void __launch_bounds__(128, 8) lei_fused_kernel(
    const float* __restrict__ x,
    const float* __restrict__ head_w,
    const float* __restrict__ head_b,
    const float* __restrict__ foot_w,
    const float* __restrict__ foot_b,
    float* __restrict__ out)
{
    const int warp = threadIdx.x >> 5;
    const int lane = threadIdx.x & 31;
    const int b = blockIdx.x * 4 + warp;   // 1024 blocks * 4 warps = 4096

    const float* __restrict__ fw0 = foot_w;            // [128]
    const float* __restrict__ fw1 = foot_w + N_NEURON; // [128]

    float acc0 = 0.0f, acc1 = 0.0f;

    // Fold the head bias contribution: sum_n head_b[n]*fw_j[n], split across lanes.
#pragma unroll
    for (int k = 0; k < 4; k++) {
        int n = 32 * k + lane;
        float hb = head_b[n];
        acc0 = fmaf(hb, fw0[n], acc0);
        acc1 = fmaf(hb, fw1[n], acc1);
    }

    const float4* __restrict__ xb =
        reinterpret_cast<const float4*>(x) + (size_t)b * (N_RULES / 4);
    const size_t nstride = (size_t)BATCH * (N_RULES / 4);  // float4 stride between neurons
    const float4* __restrict__ wq = reinterpret_cast<const float4*>(head_w);

    for (int n = 0; n < N_NEURON; n += 2) {
        // Front-batch 8 x loads (2 neurons' rows) for MLP.
        const float4* p0 = xb + (size_t)n * nstride;
        const float4* p1 = p0 + nstride;
        float4 xv[8];
#pragma unroll
        for (int k = 0; k < 4; k++) xv[k] = p0[lane + 32 * k];
#pragma unroll
        for (int k = 0; k < 4; k++) xv[4 + k] = p1[lane + 32 * k];

        float pa = 0.0f, pb = 0.0f;
#pragma unroll
        for (int k = 0; k < 4; k++) {
            float4 wv = wq[(size_t)n * (N_RULES / 4) + lane + 32 * k];
            pa = fmaf(xv[k].x, wv.x, pa);
            pa = fmaf(xv[k].y, wv.y, pa);
            pa = fmaf(xv[k].z, wv.z, pa);
            pa = fmaf(xv[k].w, wv.w, pa);
        }
#pragma unroll
        for (int k = 0; k < 4; k++) {
            float4 wv = wq[(size_t)(n + 1) * (N_RULES / 4) + lane + 32 * k];
            pb = fmaf(xv[4 + k].x, wv.x, pb);
            pb = fmaf(xv[4 + k].y, wv.y, pb);
            pb = fmaf(xv[4 + k].z, wv.z, pb);
            pb = fmaf(xv[4 + k].w, wv.w, pb);
        }

        acc0 = fmaf(pa, fw0[n], acc0);
        acc1 = fmaf(pa, fw1[n], acc1);
        acc0 = fmaf(pb, fw0[n + 1], acc0);
        acc1 = fmaf(pb, fw1[n + 1], acc1);
    }

    // Warp reduction of the two logit accumulators.
#pragma unroll
    for (int off = 16; off; off >>= 1) {
        acc0 += __shfl_xor_sync(0xFFFFFFFFu, acc0, off);
        acc1 += __shfl_xor_sync(0xFFFFFFFFu, acc1, off);
    }

    if (lane == 0) {
        float l0 = acc0 + foot_b[0];
        float l1 = acc1 + foot_b[1];
        float m  = fmaxf(l0, l1);
        float e0 = __expf(l0 - m);
        float e1 = __expf(l1 - m);
        float inv = 1.0f / (e0 + e1);
        out[b * 2 + 0] = e0 * inv;
        out[b * 2 + 1] = e1 * inv;
    }
}

extern "C" void kernel_launch(void* const* d_in, const int* in_sizes, int n_in,
                              void* d_out, int out_size)
{
    const float* x      = (const float*)d_in[0];
    const float* head_w = (const float*)d_in[1];
    const float* head_b = (const float*)d_in[2];
    const float* foot_w = (const float*)d_in[3];
    const float* foot_b = (const float*)d_in[4];
    float* out = (float*)d_out;

    // 4096 warps total, one per batch element: 1024 blocks x 128 threads.
    lei_fused_kernel<<<BATCH / 4, 128>>>(x, head_w, head_b, foot_w, foot_b, out);
}